// round 2
// baseline (speedup 1.0000x reference)
#include <cuda_runtime.h>

#define D_FEAT 64

// CSR row pointer scratch (N up to 100000 + 1). Device global: allocation-free.
__device__ int g_row_ptr[100001];

// Kernel A: row_ptr[r] = lower_bound(row, E, r) for r in [0, N].
__global__ void build_row_ptr(const int* __restrict__ row, int n, int E) {
    int r = blockIdx.x * blockDim.x + threadIdx.x;
    if (r > n) return;
    int lo = 0, hi = E;
    while (lo < hi) {
        int mid = (lo + hi) >> 1;
        if (__ldg(&row[mid]) < r) lo = mid + 1;
        else hi = mid;
    }
    g_row_ptr[r] = lo;
}

// Kernel B: one warp per output row, lane l owns features {2l, 2l+1}.
// Cooperative edge-metadata load: lane j loads (col, val) for edge base+j once
// per 32-edge chunk (2 LDGs / 32 edges instead of 64), distributed via shfl.
// This removes the per-edge broadcast loads from L1 entirely: 2 wf/edge left.
__global__ void spmm_mean_warp_per_row(const float* __restrict__ x,
                                       const float* __restrict__ vals,
                                       const int* __restrict__ col,
                                       float* __restrict__ out,
                                       int n) {
    int warp_id = (blockIdx.x * blockDim.x + threadIdx.x) >> 5;
    int lane = threadIdx.x & 31;
    if (warp_id >= n) return;

    int s = g_row_ptr[warp_id];
    int e = g_row_ptr[warp_id + 1];

    float2 acc = make_float2(0.0f, 0.0f);
    const float* xbase = x + 2 * lane;

    for (int base = s; base < e; base += 32) {
        int cnt = e - base; if (cnt > 32) cnt = 32;

        int   c_mine = 0;
        float v_mine = 0.0f;
        if (base + lane < e) {
            c_mine = __ldg(&col[base + lane]);
            v_mine = __ldg(&vals[base + lane]);
        }

        int j = 0;
        // 4-wide unroll: 4 independent gathers in flight (hide L2 ~240cyc).
        for (; j + 4 <= cnt; j += 4) {
            int   c0 = __shfl_sync(0xffffffffu, c_mine, j + 0);
            int   c1 = __shfl_sync(0xffffffffu, c_mine, j + 1);
            int   c2 = __shfl_sync(0xffffffffu, c_mine, j + 2);
            int   c3 = __shfl_sync(0xffffffffu, c_mine, j + 3);
            float v0 = __shfl_sync(0xffffffffu, v_mine, j + 0);
            float v1 = __shfl_sync(0xffffffffu, v_mine, j + 1);
            float v2 = __shfl_sync(0xffffffffu, v_mine, j + 2);
            float v3 = __shfl_sync(0xffffffffu, v_mine, j + 3);
            float2 x0 = *reinterpret_cast<const float2*>(xbase + (size_t)c0 * D_FEAT);
            float2 x1 = *reinterpret_cast<const float2*>(xbase + (size_t)c1 * D_FEAT);
            float2 x2 = *reinterpret_cast<const float2*>(xbase + (size_t)c2 * D_FEAT);
            float2 x3 = *reinterpret_cast<const float2*>(xbase + (size_t)c3 * D_FEAT);
            acc.x = fmaf(v0, x0.x, acc.x); acc.y = fmaf(v0, x0.y, acc.y);
            acc.x = fmaf(v1, x1.x, acc.x); acc.y = fmaf(v1, x1.y, acc.y);
            acc.x = fmaf(v2, x2.x, acc.x); acc.y = fmaf(v2, x2.y, acc.y);
            acc.x = fmaf(v3, x3.x, acc.x); acc.y = fmaf(v3, x3.y, acc.y);
        }
        for (; j < cnt; j++) {
            int   c = __shfl_sync(0xffffffffu, c_mine, j);
            float v = __shfl_sync(0xffffffffu, v_mine, j);
            float2 xv = *reinterpret_cast<const float2*>(xbase + (size_t)c * D_FEAT);
            acc.x = fmaf(v, xv.x, acc.x);
            acc.y = fmaf(v, xv.y, acc.y);
        }
    }

    int deg = e - s;
    float inv = 1.0f / (float)(deg > 0 ? deg : 1);
    acc.x *= inv;
    acc.y *= inv;

    *reinterpret_cast<float2*>(&out[(size_t)warp_id * D_FEAT + 2 * lane]) = acc;
}

extern "C" void kernel_launch(void* const* d_in, const int* in_sizes, int n_in,
                              void* d_out, int out_size) {
    const float* x    = (const float*)d_in[0];
    const float* vals = (const float*)d_in[1];
    const int*   row  = (const int*)d_in[2];
    const int*   col  = (const int*)d_in[3];
    float* out = (float*)d_out;

    int n = in_sizes[0] / D_FEAT;   // 100000
    int E = in_sizes[1];            // 1200000

    {
        int threads = 256;
        int blocks = (n + 1 + threads - 1) / threads;
        build_row_ptr<<<blocks, threads>>>(row, n, E);
    }
    {
        int threads = 256;
        int rows_per_block = threads / 32;
        int blocks = (n + rows_per_block - 1) / rows_per_block;
        spmm_mean_warp_per_row<<<blocks, threads>>>(x, vals, col, out, n);
    }
}

// round 3
// speedup vs baseline: 1.1000x; 1.1000x over previous
#include <cuda_runtime.h>

#define D_FEAT 64

__device__ int g_row_ptr[100001];

// Kernel A: row_ptr[r] = lower_bound(row, E, r).
__global__ void build_row_ptr(const int* __restrict__ row, int n, int E) {
    int r = blockIdx.x * blockDim.x + threadIdx.x;
    if (r > n) return;
    int lo = 0, hi = E;
    while (lo < hi) {
        int mid = (lo + hi) >> 1;
        if (__ldg(&row[mid]) < r) lo = mid + 1;
        else hi = mid;
    }
    g_row_ptr[r] = lo;
}

// Kernel B: one warp per row. Half-warp h (lanes 16h..16h+15) processes edges
// s+2j+h; each lane owns 4 features (float4). One col/vals LDG covers 2 edges
// (adjacent addresses, 1 sector). 3 L1 wavefronts per edge; 8-edge unrolled
// main loop gives 4 independent gathers in flight per half-warp.
__global__ void spmm_mean_warp_per_row(const float* __restrict__ x,
                                       const float* __restrict__ vals,
                                       const int* __restrict__ col,
                                       float* __restrict__ out,
                                       int n) {
    int warp_id = (blockIdx.x * blockDim.x + threadIdx.x) >> 5;
    int lane = threadIdx.x & 31;
    if (warp_id >= n) return;

    int s = g_row_ptr[warp_id];
    int e = g_row_ptr[warp_id + 1];

    int half = lane >> 4;       // 0 or 1
    int hl   = lane & 15;       // 0..15
    const float* xb = x + hl * 4;

    float4 acc = make_float4(0.f, 0.f, 0.f, 0.f);

    int base = s;
    // Main loop: 8 edges per warp-iteration, 4 per half-warp (MLP=4/half).
    for (; base + 8 <= e; base += 8) {
        int   c0 = __ldg(&col[base + 0 + half]);
        int   c1 = __ldg(&col[base + 2 + half]);
        int   c2 = __ldg(&col[base + 4 + half]);
        int   c3 = __ldg(&col[base + 6 + half]);
        float v0 = __ldg(&vals[base + 0 + half]);
        float v1 = __ldg(&vals[base + 2 + half]);
        float v2 = __ldg(&vals[base + 4 + half]);
        float v3 = __ldg(&vals[base + 6 + half]);
        float4 x0 = *reinterpret_cast<const float4*>(xb + (size_t)c0 * D_FEAT);
        float4 x1 = *reinterpret_cast<const float4*>(xb + (size_t)c1 * D_FEAT);
        float4 x2 = *reinterpret_cast<const float4*>(xb + (size_t)c2 * D_FEAT);
        float4 x3 = *reinterpret_cast<const float4*>(xb + (size_t)c3 * D_FEAT);
        acc.x = fmaf(v0, x0.x, acc.x); acc.y = fmaf(v0, x0.y, acc.y);
        acc.z = fmaf(v0, x0.z, acc.z); acc.w = fmaf(v0, x0.w, acc.w);
        acc.x = fmaf(v1, x1.x, acc.x); acc.y = fmaf(v1, x1.y, acc.y);
        acc.z = fmaf(v1, x1.z, acc.z); acc.w = fmaf(v1, x1.w, acc.w);
        acc.x = fmaf(v2, x2.x, acc.x); acc.y = fmaf(v2, x2.y, acc.y);
        acc.z = fmaf(v2, x2.z, acc.z); acc.w = fmaf(v2, x2.w, acc.w);
        acc.x = fmaf(v3, x3.x, acc.x); acc.y = fmaf(v3, x3.y, acc.y);
        acc.z = fmaf(v3, x3.z, acc.z); acc.w = fmaf(v3, x3.w, acc.w);
    }
    // 4-edge step.
    for (; base + 4 <= e; base += 4) {
        int   c0 = __ldg(&col[base + 0 + half]);
        int   c1 = __ldg(&col[base + 2 + half]);
        float v0 = __ldg(&vals[base + 0 + half]);
        float v1 = __ldg(&vals[base + 2 + half]);
        float4 x0 = *reinterpret_cast<const float4*>(xb + (size_t)c0 * D_FEAT);
        float4 x1 = *reinterpret_cast<const float4*>(xb + (size_t)c1 * D_FEAT);
        acc.x = fmaf(v0, x0.x, acc.x); acc.y = fmaf(v0, x0.y, acc.y);
        acc.z = fmaf(v0, x0.z, acc.z); acc.w = fmaf(v0, x0.w, acc.w);
        acc.x = fmaf(v1, x1.x, acc.x); acc.y = fmaf(v1, x1.y, acc.y);
        acc.z = fmaf(v1, x1.z, acc.z); acc.w = fmaf(v1, x1.w, acc.w);
    }
    // Remainder: up to 3 edges, predicated per half-warp.
    for (; base < e; base += 2) {
        int idx = base + half;
        if (idx < e) {
            int   c = __ldg(&col[idx]);
            float v = __ldg(&vals[idx]);
            float4 xv = *reinterpret_cast<const float4*>(xb + (size_t)c * D_FEAT);
            acc.x = fmaf(v, xv.x, acc.x); acc.y = fmaf(v, xv.y, acc.y);
            acc.z = fmaf(v, xv.z, acc.z); acc.w = fmaf(v, xv.w, acc.w);
        }
    }

    // Combine the two halves (once per row).
    acc.x += __shfl_xor_sync(0xffffffffu, acc.x, 16);
    acc.y += __shfl_xor_sync(0xffffffffu, acc.y, 16);
    acc.z += __shfl_xor_sync(0xffffffffu, acc.z, 16);
    acc.w += __shfl_xor_sync(0xffffffffu, acc.w, 16);

    int deg = e - s;
    float inv = 1.0f / (float)(deg > 0 ? deg : 1);

    if (half == 0) {
        float4 o = make_float4(acc.x * inv, acc.y * inv, acc.z * inv, acc.w * inv);
        *reinterpret_cast<float4*>(&out[(size_t)warp_id * D_FEAT + hl * 4]) = o;
    }
}

extern "C" void kernel_launch(void* const* d_in, const int* in_sizes, int n_in,
                              void* d_out, int out_size) {
    const float* x    = (const float*)d_in[0];
    const float* vals = (const float*)d_in[1];
    const int*   row  = (const int*)d_in[2];
    const int*   col  = (const int*)d_in[3];
    float* out = (float*)d_out;

    int n = in_sizes[0] / D_FEAT;   // 100000
    int E = in_sizes[1];            // 1200000

    {
        int threads = 256;
        int blocks = (n + 1 + threads - 1) / threads;
        build_row_ptr<<<blocks, threads>>>(row, n, E);
    }
    {
        int threads = 256;
        int rows_per_block = threads / 32;
        int blocks = (n + rows_per_block - 1) / rows_per_block;
        spmm_mean_warp_per_row<<<blocks, threads>>>(x, vals, col, out, n);
    }
}

// round 4
// speedup vs baseline: 1.1265x; 1.0241x over previous
#include <cuda_runtime.h>

#define D_FEAT 64

__device__ int g_row_ptr[100001];

// Kernel A: row_ptr[r] = lower_bound(row, E, r).
__global__ void build_row_ptr(const int* __restrict__ row, int n, int E) {
    int r = blockIdx.x * blockDim.x + threadIdx.x;
    if (r > n) return;
    int lo = 0, hi = E;
    while (lo < hi) {
        int mid = (lo + hi) >> 1;
        if (__ldg(&row[mid]) < r) lo = mid + 1;
        else hi = mid;
    }
    g_row_ptr[r] = lo;
}

// Kernel B: one warp per row (R1 layout: lane owns features {2l,2l+1} as float2).
// Change vs R1: per-quad metadata via ONE int4 + ONE float4 broadcast load
// (2 wavefronts/quad instead of 8), with a <=3-edge scalar prologue to align
// the quad base to 16B. Two independent accumulator pairs break the FMA chain.
__global__ void spmm_mean_warp_per_row(const float* __restrict__ x,
                                       const float* __restrict__ vals,
                                       const int* __restrict__ col,
                                       float* __restrict__ out,
                                       int n) {
    int warp_id = (blockIdx.x * blockDim.x + threadIdx.x) >> 5;
    int lane = threadIdx.x & 31;
    if (warp_id >= n) return;

    int s = g_row_ptr[warp_id];
    int e = g_row_ptr[warp_id + 1];

    const float* xb = x + 2 * lane;
    float2 a0 = make_float2(0.f, 0.f);
    float2 a1 = make_float2(0.f, 0.f);

    int i = s;

    // Prologue: align i to a multiple of 4 (<=3 scalar edges).
    int pre = (4 - (i & 3)) & 3;
    if (pre > e - i) pre = e - i;
    for (int k = 0; k < pre; k++, i++) {
        int   c = __ldg(&col[i]);
        float v = __ldg(&vals[i]);
        float2 xv = *reinterpret_cast<const float2*>(xb + (size_t)c * D_FEAT);
        a0.x = fmaf(v, xv.x, a0.x);
        a0.y = fmaf(v, xv.y, a0.y);
    }

    // Main loop: 4 edges per iteration, vectorized metadata (16B-aligned).
    for (; i + 4 <= e; i += 4) {
        int4   c = __ldg(reinterpret_cast<const int4*>(&col[i]));
        float4 v = __ldg(reinterpret_cast<const float4*>(&vals[i]));
        float2 x0 = *reinterpret_cast<const float2*>(xb + (size_t)c.x * D_FEAT);
        float2 x1 = *reinterpret_cast<const float2*>(xb + (size_t)c.y * D_FEAT);
        float2 x2 = *reinterpret_cast<const float2*>(xb + (size_t)c.z * D_FEAT);
        float2 x3 = *reinterpret_cast<const float2*>(xb + (size_t)c.w * D_FEAT);
        a0.x = fmaf(v.x, x0.x, a0.x); a0.y = fmaf(v.x, x0.y, a0.y);
        a1.x = fmaf(v.y, x1.x, a1.x); a1.y = fmaf(v.y, x1.y, a1.y);
        a0.x = fmaf(v.z, x2.x, a0.x); a0.y = fmaf(v.z, x2.y, a0.y);
        a1.x = fmaf(v.w, x3.x, a1.x); a1.y = fmaf(v.w, x3.y, a1.y);
    }

    // Tail: <=3 scalar edges.
    for (; i < e; i++) {
        int   c = __ldg(&col[i]);
        float v = __ldg(&vals[i]);
        float2 xv = *reinterpret_cast<const float2*>(xb + (size_t)c * D_FEAT);
        a0.x = fmaf(v, xv.x, a0.x);
        a0.y = fmaf(v, xv.y, a0.y);
    }

    int deg = e - s;
    float inv = 1.0f / (float)(deg > 0 ? deg : 1);
    float2 o = make_float2((a0.x + a1.x) * inv, (a0.y + a1.y) * inv);

    *reinterpret_cast<float2*>(&out[(size_t)warp_id * D_FEAT + 2 * lane]) = o;
}

extern "C" void kernel_launch(void* const* d_in, const int* in_sizes, int n_in,
                              void* d_out, int out_size) {
    const float* x    = (const float*)d_in[0];
    const float* vals = (const float*)d_in[1];
    const int*   row  = (const int*)d_in[2];
    const int*   col  = (const int*)d_in[3];
    float* out = (float*)d_out;

    int n = in_sizes[0] / D_FEAT;   // 100000
    int E = in_sizes[1];            // 1200000

    {
        int threads = 256;
        int blocks = (n + 1 + threads - 1) / threads;
        build_row_ptr<<<blocks, threads>>>(row, n, E);
    }
    {
        int threads = 256;
        int rows_per_block = threads / 32;
        int blocks = (n + rows_per_block - 1) / rows_per_block;
        spmm_mean_warp_per_row<<<blocks, threads>>>(x, vals, col, out, n);
    }
}